// round 16
// baseline (speedup 1.0000x reference)
#include <cuda_runtime.h>
#include <cuda_fp16.h>
#include <math.h>
#include <stdint.h>

// Problem constants
#define BSZ   512
#define DD    64
#define DE    65
#define JK    4225      // 65*65
#define JKP   4256      // JK padded to 133*32 (chunk-aligned per i)
#define NOUT  256
#define KTOT  274625    // 65^3
#define KPAD2 276640    // 65 * JKP
#define NCH2  8645      // KPAD2/32 = 65*133
#define ZSPLIT 37
#define CH_PER2 234     // ceil(8645/37); last split has 221

#define WSCALE   1024.0f
#define WSCALE_INV (1.0f/1024.0f)

// Scratch (static device arrays only)
__device__ float g_oe[3 * BSZ * DE];            // o1e/o2e/o3e with appended 1.0
__device__ float g_part[ZSPLIT * BSZ * NOUT];   // split-K partials [z][b][o]
__device__ float g_E[BSZ * 456];                // enc2 input
__device__ __align__(128) __half g_Wh[(size_t)NOUT * KPAD2]; // W*1024 fp16, per-i padded
__device__ __align__(128) __half g_Ph[(size_t)BSZ * JKP];    // P[b][jk] = o2*o3 fp16 (4.3MB)

struct Ptrs { const float* p[25]; };

__device__ __forceinline__ uint32_t smem_u32(const void* p) {
    uint32_t a;
    asm("{ .reg .u64 t; cvta.to.shared.u64 t, %1; cvt.u32.u64 %0, t; }" : "=r"(a) : "l"(p));
    return a;
}
__device__ __forceinline__ void cp_async16(uint32_t dst, const void* src) {
    asm volatile("cp.async.cg.shared.global [%0], [%1], 16;" :: "r"(dst), "l"(src) : "memory");
}
__device__ __forceinline__ void ldsm_x4(uint32_t* r, uint32_t addr) {
    asm volatile("ldmatrix.sync.aligned.m8n8.x4.shared.b16 {%0,%1,%2,%3}, [%4];"
        : "=r"(r[0]), "=r"(r[1]), "=r"(r[2]), "=r"(r[3]) : "r"(addr));
}
__device__ __forceinline__ void mma_f16(float* d, const uint32_t* a, const uint32_t* b) {
    asm volatile("mma.sync.aligned.m16n8k16.row.col.f32.f16.f16.f32 "
        "{%0,%1,%2,%3}, {%4,%5,%6,%7}, {%8,%9}, {%0,%1,%2,%3};"
        : "+f"(d[0]), "+f"(d[1]), "+f"(d[2]), "+f"(d[3])
        : "r"(a[0]), "r"(a[1]), "r"(a[2]), "r"(a[3]), "r"(b[0]), "r"(b[1]));
}
__device__ __forceinline__ unsigned long long dup2(float x) {
    unsigned long long r;
    asm("mov.b64 %0, {%1, %1};" : "=l"(r) : "r"(__float_as_uint(x)));
    return r;
}
__device__ __forceinline__ void fma2(unsigned long long& acc, unsigned long long a, unsigned long long b) {
    asm("fma.rn.f32x2 %0, %1, %2, %0;" : "+l"(acc) : "l"(a), "l"(b));
}

// ---------------------------------------------------------------------------
// Kernel A: prep W -> fp16 plane (scaled by 1024), per-i padded layout
// ---------------------------------------------------------------------------
__global__ __launch_bounds__(256) void k_prepW(const float* __restrict__ W) {
    int row = blockIdx.y;
    int k2 = (blockIdx.x * 256 + threadIdx.x) * 2;
    if (k2 >= KPAD2) return;
    int i = k2 / JKP;
    int jk = k2 - i * JKP;
    size_t src = (size_t)row * KTOT + (size_t)i * JK + jk;
    float w0 = (jk     < JK) ? W[src]     * WSCALE : 0.f;
    float w1 = (jk + 1 < JK) ? W[src + 1] * WSCALE : 0.f;
    *(__half2*)&g_Wh[(size_t)row * KPAD2 + k2] =
        __halves2half2(__float2half_rn(w0), __float2half_rn(w1));
}

// ---------------------------------------------------------------------------
// Kernel 1: gated branches, SMEM-staged weights (coalesced zw slabs).
// ---------------------------------------------------------------------------
#define SMEM_BR ((3*16*64 + 2*64*65 + 64*65 + 16*64) * 4)   // 66304 B

__global__ __launch_bounds__(256) void k_branches(Ptrs P) {
    extern __shared__ float sm[];
    float* vs  = sm;               // [3][16][64]
    float* zsb = sm + 3072;        // [2][64][65]  slab [buf][j][o]
    float* ws  = zsb + 8320;       // [64][65]     staged hw / ow
    float* gsS = ws + 4160;        // [16][64]

    int b0 = blockIdx.x * 16;
    int br = blockIdx.y;
    int t = threadIdx.x;
    int o = t & 63, bg = t >> 6;

    const float* hw = P.p[3 + br * 6];
    const float* hb = P.p[4 + br * 6];
    const float* zw = P.p[5 + br * 6];
    const float* zb = P.p[6 + br * 6];
    const float* ow = P.p[7 + br * 6];
    const float* ob = P.p[8 + br * 6];
    int hv = br;
    int x1 = (br == 1) ? 1 : 0;

    #pragma unroll
    for (int q = 0; q < 4; q++) {
        int e = t + 256 * q;
        int bb = e >> 6, m = e & 63;
        vs[(0 * 16 + bb) * 64 + m] = P.p[0][(b0 + bb) * DD + m];
        vs[(1 * 16 + bb) * 64 + m] = P.p[1][(b0 + bb) * DD + m];
        vs[(2 * 16 + bb) * 64 + m] = P.p[2][(b0 + bb) * DD + m];
    }
    #pragma unroll
    for (int q = 0; q < 16; q++) {
        int e = t + 256 * q;
        int r = e >> 6, m = e & 63;
        ws[r * 65 + m] = hw[r * 64 + m];
    }
    #pragma unroll
    for (int q = 0; q < 16; q++) {
        int e = t + 256 * q;
        int oo = e >> 6, j = e & 63;
        zsb[j * 65 + oo] = zw[oo * 4096 + j];
    }
    __syncthreads();

    float hacc[4];
    #pragma unroll
    for (int q = 0; q < 4; q++) hacc[q] = hb[o];
    #pragma unroll 8
    for (int m = 0; m < DD; m++) {
        float w = ws[o * 65 + m];
        #pragma unroll
        for (int q = 0; q < 4; q++) hacc[q] += w * vs[(hv * 16 + bg * 4 + q) * 64 + m];
    }

    float zacc[4];
    #pragma unroll
    for (int q = 0; q < 4; q++) zacc[q] = zb[o];
    for (int i = 0; i < DD; i++) {
        float rt_[16];
        if (i + 1 < DD) {
            #pragma unroll
            for (int q = 0; q < 16; q++) {
                int e = t + 256 * q;
                int oo = e >> 6, j = e & 63;
                rt_[q] = zw[oo * 4096 + (i + 1) * 64 + j];
            }
        }
        const float* zc = zsb + (i & 1) * 4160;
        float s[4] = {0.f, 0.f, 0.f, 0.f};
        #pragma unroll 8
        for (int j = 0; j < DD; j++) {
            float zv = zc[j * 65 + o];
            #pragma unroll
            for (int q = 0; q < 4; q++) s[q] += zv * vs[(2 * 16 + bg * 4 + q) * 64 + j];
        }
        #pragma unroll
        for (int q = 0; q < 4; q++) zacc[q] += vs[(x1 * 16 + bg * 4 + q) * 64 + i] * s[q];
        if (i + 1 < DD) {
            float* zn = zsb + ((i + 1) & 1) * 4160;
            #pragma unroll
            for (int q = 0; q < 16; q++) {
                int e = t + 256 * q;
                int oo = e >> 6, j = e & 63;
                zn[j * 65 + oo] = rt_[q];
            }
        }
        __syncthreads();
    }

    #pragma unroll
    for (int q = 0; q < 16; q++) {
        int e = t + 256 * q;
        int r = e >> 6, m = e & 63;
        ws[r * 65 + m] = ow[r * 64 + m];
    }
    #pragma unroll
    for (int q = 0; q < 4; q++) {
        float h = fmaxf(hacc[q], 0.f);
        float sg = 1.f / (1.f + expf(-zacc[q]));
        gsS[(bg * 4 + q) * 64 + o] = h * sg;
    }
    __syncthreads();

    float oacc[4];
    #pragma unroll
    for (int q = 0; q < 4; q++) oacc[q] = ob[o];
    #pragma unroll 8
    for (int m = 0; m < DD; m++) {
        float w = ws[o * 65 + m];
        #pragma unroll
        for (int q = 0; q < 4; q++) oacc[q] += w * gsS[(bg * 4 + q) * 64 + m];
    }
    #pragma unroll
    for (int q = 0; q < 4; q++) {
        g_oe[((long long)br * BSZ + b0 + bg * 4 + q) * DE + o] = fmaxf(oacc[q], 0.f);
        if (o == 0) g_oe[((long long)br * BSZ + b0 + bg * 4 + q) * DE + DD] = 1.f;
    }
}

// ---------------------------------------------------------------------------
// Kernel 2: pair plane fp16 (L2-resident): Ph[b][jk] = o2e[b,j]*o3e[b,k]
// ---------------------------------------------------------------------------
__global__ __launch_bounds__(256) void k_pairP() {
    int b = blockIdx.x, t = threadIdx.x;
    __shared__ float s2[DE], s3[DE];
    if (t < DE)           s2[t]      = g_oe[(1 * BSZ + b) * DE + t];
    else if (t < 2 * DE)  s3[t - DE] = g_oe[(2 * BSZ + b) * DE + (t - DE)];
    __syncthreads();
    size_t base = (size_t)b * JKP;
    for (int e = t; e < JKP / 2; e += 256) {
        int jk = e * 2;
        float v0 = 0.f, v1 = 0.f;
        if (jk < JK)     v0 = s2[jk / DE] * s3[jk % DE];
        if (jk + 1 < JK) v1 = s2[(jk + 1) / DE] * s3[(jk + 1) % DE];
        *(__half2*)&g_Ph[base + jk] =
            __halves2half2(__float2half_rn(v0), __float2half_rn(v1));
    }
}

// ---------------------------------------------------------------------------
// Kernel 3: GEMM, mma.sync fp16. B-tile synthesized in the fill with the Ph
// uint4 PREFETCHED into registers one chunk ahead (L2 latency hidden under
// MMA). Incremental (i, jk) counters replace per-fill division.
// Grid (4 btiles, 37 zsplits) = 148 CTAs = one full wave.
// ---------------------------------------------------------------------------
#define SROW   80        // smem row stride (64B data + 16B pad)
#define A_ROWS 256
#define B_ROWS 128
#define BH_OFF (A_ROWS * SROW)            // 20480
#define STAGE  ((A_ROWS + B_ROWS) * SROW) // 30720
#define NST    4
#define O1_OFF (NST * STAGE)              // o1s: [128][65] fp32
#define SMEM_GEMM (NST * STAGE + 128 * 65 * 4)   // 156160

__global__ __launch_bounds__(512, 1) void k_gemm_mma() {
    extern __shared__ char smem[];
    const uint32_t sb = smem_u32(smem);
    float* o1s = (float*)(smem + O1_OFF);
    const int t = threadIdx.x, w = t >> 5, lane = t & 31;
    const int gid = lane >> 2, tig = lane & 3;
    const int warp_m = w >> 2, warp_n = w & 3;
    const int b0 = blockIdx.x * 128, z = blockIdx.y;
    const int c0 = z * CH_PER2;
    const int nch = min(c0 + CH_PER2, NCH2) - c0;

    // stage o1 for this CTA's b-range: [128][65] fp32
    for (int e = t; e < 128 * DE; e += 512) {
        int bl2 = e / DE, ii = e - bl2 * DE;
        o1s[bl2 * DE + ii] = g_oe[(size_t)(b0 + bl2) * DE + ii];
    }
    __syncthreads();

    // W cp.async descriptors: 1024 16B-xfers / 512 thr = 2
    const __half* srcw[2];
    uint32_t dstw[2];
    #pragma unroll
    for (int q = 0; q < 2; q++) {
        int e = t + 512 * q;
        int r = e >> 2, qd = e & 3;
        srcw[q] = g_Wh + (size_t)r * KPAD2 + qd * 8;
        dstw[q] = (uint32_t)(r * SROW + qd * 16);
    }
    // B-fill thread mapping: 128 rows x 4 threads, each 8 halfs
    const int bl = t >> 2;
    const int kq = (t & 3) * 8;
    const __half* pbase = g_Ph + (size_t)(b0 + bl) * JKP + kq;
    char* bdst = smem + BH_OFF + bl * SROW + kq * 2;
    const float* o1row = o1s + bl * DE;

    // ldmatrix lane-offsets (within a stage)
    uint32_t a_off[4];
    #pragma unroll
    for (int mt = 0; mt < 4; mt++)
        a_off[mt] = (uint32_t)((warp_m * 64 + mt * 16 + (lane & 15)) * SROW + (lane >> 4) * 16);
    uint32_t b_off[2];
    #pragma unroll
    for (int np = 0; np < 2; np++)
        b_off[np] = (uint32_t)(BH_OFF +
            (warp_n * 32 + np * 16 + ((lane >> 4) * 8 + (lane & 7))) * SROW +
            ((lane >> 3) & 1) * 16);

    float acc[4][4][4];
    #pragma unroll
    for (int mt = 0; mt < 4; mt++)
        #pragma unroll
        for (int nt = 0; nt < 4; nt++)
            #pragma unroll
            for (int q = 0; q < 4; q++) acc[mt][nt][q] = 0.f;

    // prologue: fill stages 0..NST-2 (W cp.async + blocking B synth — ok once)
    {
        int i0 = c0 / 133;
        int jk0 = (c0 - i0 * 133) * 32;
        int pi = i0, pjk = jk0;
        #pragma unroll
        for (int p = 0; p < NST - 1; ++p) {
            if (p < nch) {
                int kb0 = (c0 + p) * 32;
                uint32_t stb = sb + (uint32_t)(p % NST) * STAGE;
                #pragma unroll
                for (int q = 0; q < 2; q++) cp_async16(stb + dstw[q], srcw[q] + kb0);
                __half2 o1h2 = __float2half2_rn(o1row[pi]);
                uint4 pd = *(const uint4*)(pbase + pjk);
                __half2* hh = (__half2*)&pd;
                hh[0] = __hmul2(hh[0], o1h2); hh[1] = __hmul2(hh[1], o1h2);
                hh[2] = __hmul2(hh[2], o1h2); hh[3] = __hmul2(hh[3], o1h2);
                *(uint4*)(bdst + (size_t)(p % NST) * STAGE) = pd;
                pjk += 32; if (pjk == JKP) { pjk = 0; pi++; }
            }
            asm volatile("cp.async.commit_group;" ::: "memory");
        }
        // prefetch Ph for the FIRST mainloop fill (chunk c0+NST-1)
        // (pi, pjk) now point at chunk c0+NST-1
        uint4 pd_reg = make_uint4(0, 0, 0, 0);
        int pd_i = pi;
        if (NST - 1 < nch) pd_reg = *(const uint4*)(pbase + pjk);

        for (int ci = 0; ci < nch; ++ci) {
            asm volatile("cp.async.wait_group %0;" :: "n"(NST - 2) : "memory");
            __syncthreads();

            // fill stage consumed last iteration with chunk cf = ci+NST-1
            int cf = ci + NST - 1;
            if (cf < nch) {
                int kb0 = (c0 + cf) * 32;
                uint32_t stb = sb + (uint32_t)(cf % NST) * STAGE;
                #pragma unroll
                for (int q = 0; q < 2; q++) cp_async16(stb + dstw[q], srcw[q] + kb0);
                __half2 o1h2 = __float2half2_rn(o1row[pd_i]);
                uint4 pd = pd_reg;
                __half2* hh = (__half2*)&pd;
                hh[0] = __hmul2(hh[0], o1h2); hh[1] = __hmul2(hh[1], o1h2);
                hh[2] = __hmul2(hh[2], o1h2); hh[3] = __hmul2(hh[3], o1h2);
                *(uint4*)(bdst + (size_t)(cf % NST) * STAGE) = pd;
                // prefetch Ph for chunk cf+1 (consumed next iteration)
                pjk += 32; if (pjk == JKP) { pjk = 0; pi++; }
                pd_i = pi;
                if (cf + 1 < nch) pd_reg = *(const uint4*)(pbase + pjk);
            }
            asm volatile("cp.async.commit_group;" ::: "memory");

            // compute stage ci
            const uint32_t st = sb + (uint32_t)(ci % NST) * STAGE;
            #pragma unroll
            for (int kh = 0; kh < 2; ++kh) {
                uint32_t bh[4][2];
                #pragma unroll
                for (int np = 0; np < 2; np++) {
                    uint32_t r4[4];
                    ldsm_x4(r4, st + b_off[np] + kh * 32);
                    bh[np * 2][0]     = r4[0];
                    bh[np * 2][1]     = r4[1];
                    bh[np * 2 + 1][0] = r4[2];
                    bh[np * 2 + 1][1] = r4[3];
                }
                #pragma unroll
                for (int mt = 0; mt < 4; mt++) {
                    uint32_t a4[4];
                    ldsm_x4(a4, st + a_off[mt] + kh * 32);
                    #pragma unroll
                    for (int nt = 0; nt < 4; nt++)
                        mma_f16(acc[mt][nt], a4, bh[nt]);
                }
            }
        }
    }

    // epilogue: acc -> g_part[z][b][o]   (values carry the 1024x W scale)
    float* gp = g_part + (size_t)z * BSZ * NOUT;
    #pragma unroll
    for (int mt = 0; mt < 4; mt++) {
        int o = warp_m * 64 + mt * 16 + gid;
        #pragma unroll
        for (int nt = 0; nt < 4; nt++) {
            int b = b0 + warp_n * 32 + nt * 8 + tig * 2;
            gp[(size_t)b * NOUT + o]           = acc[mt][nt][0];
            gp[(size_t)(b + 1) * NOUT + o]     = acc[mt][nt][1];
            gp[(size_t)b * NOUT + o + 8]       = acc[mt][nt][2];
            gp[(size_t)(b + 1) * NOUT + o + 8] = acc[mt][nt][3];
        }
    }
}

// ---------------------------------------------------------------------------
// Kernel 4: reduce split-K partials (undo 1024x) + bias/relu + enc2 input
// ---------------------------------------------------------------------------
__global__ __launch_bounds__(256) void k_reduce(const float* __restrict__ e1b) {
    int b = blockIdx.x, t = threadIdx.x;
    float s = 0.f;
    #pragma unroll 1
    for (int zz = 0; zz < ZSPLIT; ++zz)
        s += g_part[((size_t)zz * BSZ + b) * NOUT + t];
    s = e1b[t] + s * WSCALE_INV;
    g_E[b * 456 + t] = fmaxf(s, 0.f);
    if (t < 195)
        g_E[b * 456 + 256 + t] = g_oe[((t / 65) * BSZ + b) * DE + (t % 65)];
    else if (t < 200)
        g_E[b * 456 + 451 + (t - 195)] = 0.f;
}

// ---------------------------------------------------------------------------
// Kernel 5: enc2 tiled GEMM: out[b,n] = relu(E[b,:451] . e2w[n,:451] + e2b[n])
// ---------------------------------------------------------------------------
__global__ __launch_bounds__(256) void k_enc2(const float* __restrict__ e2w,
                                              const float* __restrict__ e2b,
                                              float* __restrict__ out) {
    __shared__ __align__(16) float As[64][68];
    __shared__ __align__(16) float Bs[64][68];
    int b0 = blockIdx.x * 64, n0 = blockIdx.y * 64;
    int t = threadIdx.x;
    int m0 = (t >> 4) << 2, q0 = (t & 15) << 2;

    unsigned long long acc[4][2];
    #pragma unroll
    for (int a = 0; a < 4; a++)
        #pragma unroll
        for (int p = 0; p < 2; p++) acc[a][p] = 0ull;

    for (int kc = 0; kc < 512; kc += 64) {
        __syncthreads();
        for (int e = t; e < 64 * 64; e += 256) {
            int r = e >> 6, kk = e & 63;
            int k = kc + kk;
            As[kk][r] = (k < 451) ? e2w[(n0 + r) * 451 + k] : 0.f;
            Bs[kk][r] = (k < 451) ? g_E[(b0 + r) * 456 + k] : 0.f;
        }
        __syncthreads();
        #pragma unroll 16
        for (int kk = 0; kk < 64; ++kk) {
            float4 a4 = *(const float4*)&As[kk][m0];
            ulonglong2 bb = *(const ulonglong2*)&Bs[kk][q0];
            unsigned long long a0 = dup2(a4.x), a1 = dup2(a4.y),
                               a2 = dup2(a4.z), a3 = dup2(a4.w);
            fma2(acc[0][0], a0, bb.x); fma2(acc[0][1], a0, bb.y);
            fma2(acc[1][0], a1, bb.x); fma2(acc[1][1], a1, bb.y);
            fma2(acc[2][0], a2, bb.x); fma2(acc[2][1], a2, bb.y);
            fma2(acc[3][0], a3, bb.x); fma2(acc[3][1], a3, bb.y);
        }
    }

    #pragma unroll
    for (int mi = 0; mi < 4; ++mi) {
        int n = n0 + m0 + mi;
        float bias = e2b[n];
        #pragma unroll
        for (int p = 0; p < 2; ++p) {
            unsigned long long v = acc[mi][p];
            float lo = __uint_as_float((unsigned)v);
            float hi = __uint_as_float((unsigned)(v >> 32));
            out[(b0 + q0 + 2 * p)     * NOUT + n] = fmaxf(lo + bias, 0.f);
            out[(b0 + q0 + 2 * p + 1) * NOUT + n] = fmaxf(hi + bias, 0.f);
        }
    }
}

// ---------------------------------------------------------------------------
extern "C" void kernel_launch(void* const* d_in, const int* in_sizes, int n_in,
                              void* d_out, int out_size) {
    Ptrs P;
    for (int i = 0; i < 25; i++) P.p[i] = (const float*)d_in[i];

    cudaFuncSetAttribute(k_gemm_mma, cudaFuncAttributeMaxDynamicSharedMemorySize, SMEM_GEMM);
    cudaFuncSetAttribute(k_branches, cudaFuncAttributeMaxDynamicSharedMemorySize, SMEM_BR);

    k_prepW<<<dim3((KPAD2 / 2 + 255) / 256, 256), 256>>>((const float*)d_in[21]);
    k_branches<<<dim3(32, 3), 256, SMEM_BR>>>(P);
    k_pairP<<<512, 256>>>();
    k_gemm_mma<<<dim3(4, ZSPLIT), 512, SMEM_GEMM>>>();
    k_reduce<<<512, 256>>>((const float*)d_in[22]);
    k_enc2<<<dim3(8, 4), 256>>>((const float*)d_in[23], (const float*)d_in[24], (float*)d_out);
}

// round 17
// speedup vs baseline: 1.0491x; 1.0491x over previous
#include <cuda_runtime.h>
#include <cuda_fp16.h>
#include <math.h>
#include <stdint.h>

// Problem constants
#define BSZ   512
#define DD    64
#define DE    65
#define JK    4225      // 65*65
#define JKP   4256      // JK padded to 133*32 (chunk-aligned per i)
#define NOUT  256
#define KTOT  274625    // 65^3
#define KPAD2 276640    // 65 * JKP
#define NCH2  8645      // KPAD2/32 = 65*133
#define ZSPLIT 37
#define CH_PER2 234     // ceil(8645/37); last split has 221

#define WSCALE   1024.0f
#define WSCALE_INV (1.0f/1024.0f)

// Scratch (static device arrays only)
__device__ float g_oe[3 * BSZ * DE];            // o1e/o2e/o3e with appended 1.0
__device__ float g_part[ZSPLIT * BSZ * NOUT];   // split-K partials [z][b][o]
__device__ float g_E[BSZ * 456];                // enc2 input
__device__ __align__(128) __half g_Wh[(size_t)NOUT * KPAD2]; // W*1024 fp16, per-i padded
__device__ __align__(128) __half g_Ph[(size_t)BSZ * JKP];    // P[b][jk] = o2*o3 fp16 (4.3MB)

struct Ptrs { const float* p[25]; };

__device__ __forceinline__ uint32_t smem_u32(const void* p) {
    uint32_t a;
    asm("{ .reg .u64 t; cvta.to.shared.u64 t, %1; cvt.u32.u64 %0, t; }" : "=r"(a) : "l"(p));
    return a;
}
__device__ __forceinline__ void cp_async16(uint32_t dst, const void* src) {
    asm volatile("cp.async.cg.shared.global [%0], [%1], 16;" :: "r"(dst), "l"(src) : "memory");
}
__device__ __forceinline__ void ldsm_x4(uint32_t* r, uint32_t addr) {
    asm volatile("ldmatrix.sync.aligned.m8n8.x4.shared.b16 {%0,%1,%2,%3}, [%4];"
        : "=r"(r[0]), "=r"(r[1]), "=r"(r[2]), "=r"(r[3]) : "r"(addr));
}
__device__ __forceinline__ void mma_f16(float* d, const uint32_t* a, const uint32_t* b) {
    asm volatile("mma.sync.aligned.m16n8k16.row.col.f32.f16.f16.f32 "
        "{%0,%1,%2,%3}, {%4,%5,%6,%7}, {%8,%9}, {%0,%1,%2,%3};"
        : "+f"(d[0]), "+f"(d[1]), "+f"(d[2]), "+f"(d[3])
        : "r"(a[0]), "r"(a[1]), "r"(a[2]), "r"(a[3]), "r"(b[0]), "r"(b[1]));
}
__device__ __forceinline__ unsigned long long dup2(float x) {
    unsigned long long r;
    asm("mov.b64 %0, {%1, %1};" : "=l"(r) : "r"(__float_as_uint(x)));
    return r;
}
__device__ __forceinline__ void fma2(unsigned long long& acc, unsigned long long a, unsigned long long b) {
    asm("fma.rn.f32x2 %0, %1, %2, %0;" : "+l"(acc) : "l"(a), "l"(b));
}

// ---------------------------------------------------------------------------
// Kernel A: prep W -> fp16 plane (scaled by 1024), per-i padded layout
// ---------------------------------------------------------------------------
__global__ __launch_bounds__(256) void k_prepW(const float* __restrict__ W) {
    int row = blockIdx.y;
    int k2 = (blockIdx.x * 256 + threadIdx.x) * 2;
    if (k2 >= KPAD2) return;
    int i = k2 / JKP;
    int jk = k2 - i * JKP;
    size_t src = (size_t)row * KTOT + (size_t)i * JK + jk;
    float w0 = (jk     < JK) ? W[src]     * WSCALE : 0.f;
    float w1 = (jk + 1 < JK) ? W[src + 1] * WSCALE : 0.f;
    *(__half2*)&g_Wh[(size_t)row * KPAD2 + k2] =
        __halves2half2(__float2half_rn(w0), __float2half_rn(w1));
}

// ---------------------------------------------------------------------------
// Kernel 1: gated branches, SMEM-staged weights (coalesced zw slabs).
// ---------------------------------------------------------------------------
#define SMEM_BR ((3*16*64 + 2*64*65 + 64*65 + 16*64) * 4)   // 66304 B

__global__ __launch_bounds__(256) void k_branches(Ptrs P) {
    extern __shared__ float sm[];
    float* vs  = sm;               // [3][16][64]
    float* zsb = sm + 3072;        // [2][64][65]  slab [buf][j][o]
    float* ws  = zsb + 8320;       // [64][65]     staged hw / ow
    float* gsS = ws + 4160;        // [16][64]

    int b0 = blockIdx.x * 16;
    int br = blockIdx.y;
    int t = threadIdx.x;
    int o = t & 63, bg = t >> 6;

    const float* hw = P.p[3 + br * 6];
    const float* hb = P.p[4 + br * 6];
    const float* zw = P.p[5 + br * 6];
    const float* zb = P.p[6 + br * 6];
    const float* ow = P.p[7 + br * 6];
    const float* ob = P.p[8 + br * 6];
    int hv = br;
    int x1 = (br == 1) ? 1 : 0;

    #pragma unroll
    for (int q = 0; q < 4; q++) {
        int e = t + 256 * q;
        int bb = e >> 6, m = e & 63;
        vs[(0 * 16 + bb) * 64 + m] = P.p[0][(b0 + bb) * DD + m];
        vs[(1 * 16 + bb) * 64 + m] = P.p[1][(b0 + bb) * DD + m];
        vs[(2 * 16 + bb) * 64 + m] = P.p[2][(b0 + bb) * DD + m];
    }
    #pragma unroll
    for (int q = 0; q < 16; q++) {
        int e = t + 256 * q;
        int r = e >> 6, m = e & 63;
        ws[r * 65 + m] = hw[r * 64 + m];
    }
    #pragma unroll
    for (int q = 0; q < 16; q++) {
        int e = t + 256 * q;
        int oo = e >> 6, j = e & 63;
        zsb[j * 65 + oo] = zw[oo * 4096 + j];
    }
    __syncthreads();

    float hacc[4];
    #pragma unroll
    for (int q = 0; q < 4; q++) hacc[q] = hb[o];
    #pragma unroll 8
    for (int m = 0; m < DD; m++) {
        float w = ws[o * 65 + m];
        #pragma unroll
        for (int q = 0; q < 4; q++) hacc[q] += w * vs[(hv * 16 + bg * 4 + q) * 64 + m];
    }

    float zacc[4];
    #pragma unroll
    for (int q = 0; q < 4; q++) zacc[q] = zb[o];
    for (int i = 0; i < DD; i++) {
        float rt_[16];
        if (i + 1 < DD) {
            #pragma unroll
            for (int q = 0; q < 16; q++) {
                int e = t + 256 * q;
                int oo = e >> 6, j = e & 63;
                rt_[q] = zw[oo * 4096 + (i + 1) * 64 + j];
            }
        }
        const float* zc = zsb + (i & 1) * 4160;
        float s[4] = {0.f, 0.f, 0.f, 0.f};
        #pragma unroll 8
        for (int j = 0; j < DD; j++) {
            float zv = zc[j * 65 + o];
            #pragma unroll
            for (int q = 0; q < 4; q++) s[q] += zv * vs[(2 * 16 + bg * 4 + q) * 64 + j];
        }
        #pragma unroll
        for (int q = 0; q < 4; q++) zacc[q] += vs[(x1 * 16 + bg * 4 + q) * 64 + i] * s[q];
        if (i + 1 < DD) {
            float* zn = zsb + ((i + 1) & 1) * 4160;
            #pragma unroll
            for (int q = 0; q < 16; q++) {
                int e = t + 256 * q;
                int oo = e >> 6, j = e & 63;
                zn[j * 65 + oo] = rt_[q];
            }
        }
        __syncthreads();
    }

    #pragma unroll
    for (int q = 0; q < 16; q++) {
        int e = t + 256 * q;
        int r = e >> 6, m = e & 63;
        ws[r * 65 + m] = ow[r * 64 + m];
    }
    #pragma unroll
    for (int q = 0; q < 4; q++) {
        float h = fmaxf(hacc[q], 0.f);
        float sg = 1.f / (1.f + expf(-zacc[q]));
        gsS[(bg * 4 + q) * 64 + o] = h * sg;
    }
    __syncthreads();

    float oacc[4];
    #pragma unroll
    for (int q = 0; q < 4; q++) oacc[q] = ob[o];
    #pragma unroll 8
    for (int m = 0; m < DD; m++) {
        float w = ws[o * 65 + m];
        #pragma unroll
        for (int q = 0; q < 4; q++) oacc[q] += w * gsS[(bg * 4 + q) * 64 + m];
    }
    #pragma unroll
    for (int q = 0; q < 4; q++) {
        g_oe[((long long)br * BSZ + b0 + bg * 4 + q) * DE + o] = fmaxf(oacc[q], 0.f);
        if (o == 0) g_oe[((long long)br * BSZ + b0 + bg * 4 + q) * DE + DD] = 1.f;
    }
}

// ---------------------------------------------------------------------------
// Kernel 2: pair plane fp16 (L2-resident): Ph[b][jk] = o2e[b,j]*o3e[b,k]
// ---------------------------------------------------------------------------
__global__ __launch_bounds__(256) void k_pairP() {
    int b = blockIdx.x, t = threadIdx.x;
    __shared__ float s2[DE], s3[DE];
    if (t < DE)           s2[t]      = g_oe[(1 * BSZ + b) * DE + t];
    else if (t < 2 * DE)  s3[t - DE] = g_oe[(2 * BSZ + b) * DE + (t - DE)];
    __syncthreads();
    size_t base = (size_t)b * JKP;
    for (int e = t; e < JKP / 2; e += 256) {
        int jk = e * 2;
        float v0 = 0.f, v1 = 0.f;
        if (jk < JK)     v0 = s2[jk / DE] * s3[jk % DE];
        if (jk + 1 < JK) v1 = s2[(jk + 1) / DE] * s3[(jk + 1) % DE];
        *(__half2*)&g_Ph[base + jk] =
            __halves2half2(__float2half_rn(v0), __float2half_rn(v1));
    }
}

// ---------------------------------------------------------------------------
// Kernel 3: GEMM, mma.sync fp16. B-tile synthesized from register-prefetched
// Ph + o1 AFTER the compute block (synth chain drains under MMA issue, never
// blocks LDSM). W via cp.async. Single sync/chunk, 4 stages.
// Grid (4 btiles, 37 zsplits) = 148 CTAs = one full wave.
// ---------------------------------------------------------------------------
#define SROW   80        // smem row stride (64B data + 16B pad)
#define A_ROWS 256
#define B_ROWS 128
#define BH_OFF (A_ROWS * SROW)            // 20480
#define STAGE  ((A_ROWS + B_ROWS) * SROW) // 30720
#define NST    4
#define O1_OFF (NST * STAGE)              // o1s: [128][65] fp32
#define SMEM_GEMM (NST * STAGE + 128 * 65 * 4)   // 156160

__global__ __launch_bounds__(512, 1) void k_gemm_mma() {
    extern __shared__ char smem[];
    const uint32_t sb = smem_u32(smem);
    float* o1s = (float*)(smem + O1_OFF);
    const int t = threadIdx.x, w = t >> 5, lane = t & 31;
    const int gid = lane >> 2, tig = lane & 3;
    const int warp_m = w >> 2, warp_n = w & 3;
    const int b0 = blockIdx.x * 128, z = blockIdx.y;
    const int c0 = z * CH_PER2;
    const int nch = min(c0 + CH_PER2, NCH2) - c0;

    // stage o1 for this CTA's b-range: [128][65] fp32
    for (int e = t; e < 128 * DE; e += 512) {
        int bl2 = e / DE, ii = e - bl2 * DE;
        o1s[bl2 * DE + ii] = g_oe[(size_t)(b0 + bl2) * DE + ii];
    }
    __syncthreads();

    // W cp.async descriptors: 1024 16B-xfers / 512 thr = 2
    const __half* srcw[2];
    uint32_t dstw[2];
    #pragma unroll
    for (int q = 0; q < 2; q++) {
        int e = t + 512 * q;
        int r = e >> 2, qd = e & 3;
        srcw[q] = g_Wh + (size_t)r * KPAD2 + qd * 8;
        dstw[q] = (uint32_t)(r * SROW + qd * 16);
    }
    // B-fill thread mapping: 128 rows x 4 threads, each 8 halfs
    const int bl = t >> 2;
    const int kq = (t & 3) * 8;
    const __half* pbase = g_Ph + (size_t)(b0 + bl) * JKP + kq;
    char* bdst = smem + BH_OFF + bl * SROW + kq * 2;
    const float* o1row = o1s + bl * DE;

    // ldmatrix lane-offsets (within a stage)
    uint32_t a_off[4];
    #pragma unroll
    for (int mt = 0; mt < 4; mt++)
        a_off[mt] = (uint32_t)((warp_m * 64 + mt * 16 + (lane & 15)) * SROW + (lane >> 4) * 16);
    uint32_t b_off[2];
    #pragma unroll
    for (int np = 0; np < 2; np++)
        b_off[np] = (uint32_t)(BH_OFF +
            (warp_n * 32 + np * 16 + ((lane >> 4) * 8 + (lane & 7))) * SROW +
            ((lane >> 3) & 1) * 16);

    float acc[4][4][4];
    #pragma unroll
    for (int mt = 0; mt < 4; mt++)
        #pragma unroll
        for (int nt = 0; nt < 4; nt++)
            #pragma unroll
            for (int q = 0; q < 4; q++) acc[mt][nt][q] = 0.f;

    // prologue: fill stages 0..NST-2 (W cp.async + blocking B synth — ok once)
    int pi = c0 / 133;
    int pjk = (c0 - pi * 133) * 32;
    #pragma unroll
    for (int p = 0; p < NST - 1; ++p) {
        if (p < nch) {
            int kb0 = (c0 + p) * 32;
            uint32_t stb = sb + (uint32_t)(p % NST) * STAGE;
            #pragma unroll
            for (int q = 0; q < 2; q++) cp_async16(stb + dstw[q], srcw[q] + kb0);
            __half2 o1h2 = __float2half2_rn(o1row[pi]);
            uint4 pd = *(const uint4*)(pbase + pjk);
            __half2* hh = (__half2*)&pd;
            hh[0] = __hmul2(hh[0], o1h2); hh[1] = __hmul2(hh[1], o1h2);
            hh[2] = __hmul2(hh[2], o1h2); hh[3] = __hmul2(hh[3], o1h2);
            *(uint4*)(bdst + (size_t)(p % NST) * STAGE) = pd;
            pjk += 32; if (pjk == JKP) { pjk = 0; pi++; }
        }
        asm volatile("cp.async.commit_group;" ::: "memory");
    }
    // prefetch Ph + o1 for the FIRST mainloop fill (chunk c0+NST-1)
    uint4 pd_reg = make_uint4(0, 0, 0, 0);
    __half2 o1h2_reg = __float2half2_rn(0.f);
    if (NST - 1 < nch) {
        pd_reg = *(const uint4*)(pbase + pjk);
        o1h2_reg = __float2half2_rn(o1row[pi]);
    }

    for (int ci = 0; ci < nch; ++ci) {
        asm volatile("cp.async.wait_group %0;" :: "n"(NST - 2) : "memory");
        __syncthreads();

        const int cf = ci + NST - 1;
        // issue W cp.async for stage cf early (latency)
        if (cf < nch) {
            int kb0 = (c0 + cf) * 32;
            uint32_t stb = sb + (uint32_t)(cf % NST) * STAGE;
            #pragma unroll
            for (int q = 0; q < 2; q++) cp_async16(stb + dstw[q], srcw[q] + kb0);
        }

        // compute stage ci (LDSM + MMA) — no dependency on the fill above
        const uint32_t st = sb + (uint32_t)(ci % NST) * STAGE;
        #pragma unroll
        for (int kh = 0; kh < 2; ++kh) {
            uint32_t bh[4][2];
            #pragma unroll
            for (int np = 0; np < 2; np++) {
                uint32_t r4[4];
                ldsm_x4(r4, st + b_off[np] + kh * 32);
                bh[np * 2][0]     = r4[0];
                bh[np * 2][1]     = r4[1];
                bh[np * 2 + 1][0] = r4[2];
                bh[np * 2 + 1][1] = r4[3];
            }
            #pragma unroll
            for (int mt = 0; mt < 4; mt++) {
                uint32_t a4[4];
                ldsm_x4(a4, st + a_off[mt] + kh * 32);
                #pragma unroll
                for (int nt = 0; nt < 4; nt++)
                    mma_f16(acc[mt][nt], a4, bh[nt]);
            }
        }

        // B-synth STS for stage cf AFTER compute (drains under MMA issue);
        // operands were register-prefetched last iteration
        if (cf < nch) {
            uint4 pd = pd_reg;
            __half2* hh = (__half2*)&pd;
            hh[0] = __hmul2(hh[0], o1h2_reg); hh[1] = __hmul2(hh[1], o1h2_reg);
            hh[2] = __hmul2(hh[2], o1h2_reg); hh[3] = __hmul2(hh[3], o1h2_reg);
            *(uint4*)(bdst + (size_t)(cf % NST) * STAGE) = pd;
            // prefetch Ph + o1 for chunk cf+1 (consumed next iteration)
            pjk += 32; if (pjk == JKP) { pjk = 0; pi++; }
            if (cf + 1 < nch) {
                pd_reg = *(const uint4*)(pbase + pjk);
                o1h2_reg = __float2half2_rn(o1row[pi]);
            }
        }
        asm volatile("cp.async.commit_group;" ::: "memory");
    }

    // epilogue: acc -> g_part[z][b][o]   (values carry the 1024x W scale)
    float* gp = g_part + (size_t)z * BSZ * NOUT;
    #pragma unroll
    for (int mt = 0; mt < 4; mt++) {
        int o = warp_m * 64 + mt * 16 + gid;
        #pragma unroll
        for (int nt = 0; nt < 4; nt++) {
            int b = b0 + warp_n * 32 + nt * 8 + tig * 2;
            gp[(size_t)b * NOUT + o]           = acc[mt][nt][0];
            gp[(size_t)(b + 1) * NOUT + o]     = acc[mt][nt][1];
            gp[(size_t)b * NOUT + o + 8]       = acc[mt][nt][2];
            gp[(size_t)(b + 1) * NOUT + o + 8] = acc[mt][nt][3];
        }
    }
}

// ---------------------------------------------------------------------------
// Kernel 4: reduce split-K partials (undo 1024x) + bias/relu + enc2 input
// ---------------------------------------------------------------------------
__global__ __launch_bounds__(256) void k_reduce(const float* __restrict__ e1b) {
    int b = blockIdx.x, t = threadIdx.x;
    float s = 0.f;
    #pragma unroll 1
    for (int zz = 0; zz < ZSPLIT; ++zz)
        s += g_part[((size_t)zz * BSZ + b) * NOUT + t];
    s = e1b[t] + s * WSCALE_INV;
    g_E[b * 456 + t] = fmaxf(s, 0.f);
    if (t < 195)
        g_E[b * 456 + 256 + t] = g_oe[((t / 65) * BSZ + b) * DE + (t % 65)];
    else if (t < 200)
        g_E[b * 456 + 451 + (t - 195)] = 0.f;
}

// ---------------------------------------------------------------------------
// Kernel 5: enc2 tiled GEMM: out[b,n] = relu(E[b,:451] . e2w[n,:451] + e2b[n])
// ---------------------------------------------------------------------------
__global__ __launch_bounds__(256) void k_enc2(const float* __restrict__ e2w,
                                              const float* __restrict__ e2b,
                                              float* __restrict__ out) {
    __shared__ __align__(16) float As[64][68];
    __shared__ __align__(16) float Bs[64][68];
    int b0 = blockIdx.x * 64, n0 = blockIdx.y * 64;
    int t = threadIdx.x;
    int m0 = (t >> 4) << 2, q0 = (t & 15) << 2;

    unsigned long long acc[4][2];
    #pragma unroll
    for (int a = 0; a < 4; a++)
        #pragma unroll
        for (int p = 0; p < 2; p++) acc[a][p] = 0ull;

    for (int kc = 0; kc < 512; kc += 64) {
        __syncthreads();
        for (int e = t; e < 64 * 64; e += 256) {
            int r = e >> 6, kk = e & 63;
            int k = kc + kk;
            As[kk][r] = (k < 451) ? e2w[(n0 + r) * 451 + k] : 0.f;
            Bs[kk][r] = (k < 451) ? g_E[(b0 + r) * 456 + k] : 0.f;
        }
        __syncthreads();
        #pragma unroll 16
        for (int kk = 0; kk < 64; ++kk) {
            float4 a4 = *(const float4*)&As[kk][m0];
            ulonglong2 bb = *(const ulonglong2*)&Bs[kk][q0];
            unsigned long long a0 = dup2(a4.x), a1 = dup2(a4.y),
                               a2 = dup2(a4.z), a3 = dup2(a4.w);
            fma2(acc[0][0], a0, bb.x); fma2(acc[0][1], a0, bb.y);
            fma2(acc[1][0], a1, bb.x); fma2(acc[1][1], a1, bb.y);
            fma2(acc[2][0], a2, bb.x); fma2(acc[2][1], a2, bb.y);
            fma2(acc[3][0], a3, bb.x); fma2(acc[3][1], a3, bb.y);
        }
    }

    #pragma unroll
    for (int mi = 0; mi < 4; ++mi) {
        int n = n0 + m0 + mi;
        float bias = e2b[n];
        #pragma unroll
        for (int p = 0; p < 2; ++p) {
            unsigned long long v = acc[mi][p];
            float lo = __uint_as_float((unsigned)v);
            float hi = __uint_as_float((unsigned)(v >> 32));
            out[(b0 + q0 + 2 * p)     * NOUT + n] = fmaxf(lo + bias, 0.f);
            out[(b0 + q0 + 2 * p + 1) * NOUT + n] = fmaxf(hi + bias, 0.f);
        }
    }
}

// ---------------------------------------------------------------------------
extern "C" void kernel_launch(void* const* d_in, const int* in_sizes, int n_in,
                              void* d_out, int out_size) {
    Ptrs P;
    for (int i = 0; i < 25; i++) P.p[i] = (const float*)d_in[i];

    cudaFuncSetAttribute(k_gemm_mma, cudaFuncAttributeMaxDynamicSharedMemorySize, SMEM_GEMM);
    cudaFuncSetAttribute(k_branches, cudaFuncAttributeMaxDynamicSharedMemorySize, SMEM_BR);

    k_prepW<<<dim3((KPAD2 / 2 + 255) / 256, 256), 256>>>((const float*)d_in[21]);
    k_branches<<<dim3(32, 3), 256, SMEM_BR>>>(P);
    k_pairP<<<512, 256>>>();
    k_gemm_mma<<<dim3(4, ZSPLIT), 512, SMEM_GEMM>>>();
    k_reduce<<<512, 256>>>((const float*)d_in[22]);
    k_enc2<<<dim3(8, 4), 256>>>((const float*)d_in[23], (const float*)d_in[24], (float*)d_out);
}